// round 2
// baseline (speedup 1.0000x reference)
#include <cuda_runtime.h>
#include <cuda_bf16.h>
#include <cstdint>

// ============================================================================
// out[b,f] = -0.5 * sum_d ((x[b,d]-mu[f,d])/scale[f,d])^2
// Reformulated as one GEMM + bias:
//   out = A @ W^T + bias
//   A[b,:] = [ bf16(x^2) | bf16(x) ]          (8192 x 2048) bf16
//   W[f,:] = [ bf16(-0.5*inv2) | bf16(mu*inv2) ] (4096 x 2048) bf16
//   bias[f] = -0.5 * sum_d mu^2*inv2  (fp32, exact)
// GEMM path: mma.sync.m16n8k16.bf16 (base sm_103 target — tcgen05 is
// unavailable: harness compiles via compute_103 virtual arch, no 'a' features).
// Ampere-style 4-stage cp.async pipeline, ldmatrix operand loads.
// ============================================================================

#define B_DIM 8192
#define F_DIM 4096
#define K_DIM 2048

#define BM 128
#define BN 128
#define BK 64
#define ST 4
#define LDS_ROW 72                      // 64 bf16 + 8 pad
#define ROW_BYTES (LDS_ROW * 2)         // 144 B (16B-aligned, LDSM conflict-free)
#define TILE_BYTES (BM * ROW_BYTES)     // 18432
#define STAGE_BYTES (2 * TILE_BYTES)    // 36864
#define SMEM_DYN (ST * STAGE_BYTES)     // 147456
#define KSTEPS (K_DIM / BK)             // 32

// Scratch (device globals: no allocation allowed)
__device__ __align__(16) __nv_bfloat16 g_A[(size_t)B_DIM * K_DIM];  // 32 MB
__device__ __align__(16) __nv_bfloat16 g_W[(size_t)F_DIM * K_DIM];  // 16 MB
__device__ float g_bias[F_DIM];

// ---------------------------------------------------------------------------
// helpers
// ---------------------------------------------------------------------------
__device__ __forceinline__ uint32_t smem_u32(const void* p) {
    uint32_t a;
    asm("{ .reg .u64 t; cvta.to.shared.u64 t, %1; cvt.u32.u64 %0, t; }"
        : "=r"(a) : "l"(p));
    return a;
}

__device__ __forceinline__ uint32_t pack_bf16(float a, float b) {
    uint32_t lo = (uint32_t)__bfloat16_as_ushort(__float2bfloat16(a));
    uint32_t hi = (uint32_t)__bfloat16_as_ushort(__float2bfloat16(b));
    return lo | (hi << 16);
}

#define CP_ASYNC16(dst, src) \
    asm volatile("cp.async.cg.shared.global [%0], [%1], 16;" \
                 :: "r"(dst), "l"(src) : "memory")
#define CP_COMMIT() asm volatile("cp.async.commit_group;" ::: "memory")
#define CP_WAIT2()  asm volatile("cp.async.wait_group 2;" ::: "memory")

#define LDSM_X4(r, addr) \
    asm volatile("ldmatrix.sync.aligned.m8n8.x4.shared.b16 {%0,%1,%2,%3}, [%4];" \
                 : "=r"((r)[0]), "=r"((r)[1]), "=r"((r)[2]), "=r"((r)[3]) \
                 : "r"(addr))

#define MMA_BF16(c, a, b0, b1) \
    asm volatile("mma.sync.aligned.m16n8k16.row.col.f32.bf16.bf16.f32 " \
                 "{%0,%1,%2,%3}, {%4,%5,%6,%7}, {%8,%9}, {%0,%1,%2,%3};" \
                 : "+f"((c)[0]), "+f"((c)[1]), "+f"((c)[2]), "+f"((c)[3]) \
                 : "r"((a)[0]), "r"((a)[1]), "r"((a)[2]), "r"((a)[3]), \
                   "r"(b0), "r"(b1))

// ---------------------------------------------------------------------------
// Prep 1: A = [ bf16(x^2) | bf16(x) ]   (one block per batch row)
// ---------------------------------------------------------------------------
__global__ void prep_a_kernel(const float* __restrict__ x) {
    int b = blockIdx.x;
    int t = threadIdx.x;                               // 256 threads, 4 elems each
    float4 v = reinterpret_cast<const float4*>(x)[b * 256 + t];
    uint2 sq = make_uint2(pack_bf16(v.x * v.x, v.y * v.y),
                          pack_bf16(v.z * v.z, v.w * v.w));
    uint2 vr = make_uint2(pack_bf16(v.x, v.y), pack_bf16(v.z, v.w));
    uint2* A2 = reinterpret_cast<uint2*>(g_A);
    A2[(size_t)b * 512 + t]       = sq;   // d in [0,1024):   x^2
    A2[(size_t)b * 512 + 256 + t] = vr;   // d in [1024,2048): x
}

// ---------------------------------------------------------------------------
// Prep 2: W = [ bf16(-0.5*inv2) | bf16(mu*inv2) ], bias = -0.5*sum mu^2*inv2
// ---------------------------------------------------------------------------
__global__ void prep_w_kernel(const float* __restrict__ mu,
                              const float* __restrict__ sd) {
    __shared__ float red[256];
    int f = blockIdx.x;
    int t = threadIdx.x;
    float4 m = reinterpret_cast<const float4*>(mu)[f * 256 + t];
    float4 s = reinterpret_cast<const float4*>(sd)[f * 256 + t];
    float4 i2 = make_float4(1.0f / (s.x * s.x), 1.0f / (s.y * s.y),
                            1.0f / (s.z * s.z), 1.0f / (s.w * s.w));
    uint2 w1 = make_uint2(pack_bf16(-0.5f * i2.x, -0.5f * i2.y),
                          pack_bf16(-0.5f * i2.z, -0.5f * i2.w));
    uint2 w2 = make_uint2(pack_bf16(m.x * i2.x, m.y * i2.y),
                          pack_bf16(m.z * i2.z, m.w * i2.w));
    uint2* W2 = reinterpret_cast<uint2*>(g_W);
    W2[(size_t)f * 512 + t]       = w1;
    W2[(size_t)f * 512 + 256 + t] = w2;
    red[t] = m.x * m.x * i2.x + m.y * m.y * i2.y +
             m.z * m.z * i2.z + m.w * m.w * i2.w;
    __syncthreads();
    #pragma unroll
    for (int o = 128; o > 0; o >>= 1) {
        if (t < o) red[t] += red[t + o];
        __syncthreads();
    }
    if (t == 0) g_bias[f] = -0.5f * red[0];
}

// ---------------------------------------------------------------------------
// GEMM: 128x128x64-stage tiles, 4-stage cp.async pipe, 8 warps (4m x 2n),
// warp tile 32x64, mma.sync m16n8k16 bf16 -> fp32
// ---------------------------------------------------------------------------
__global__ void __launch_bounds__(256, 1)
gemm_kernel(float* __restrict__ out) {
    extern __shared__ char smem[];
    const uint32_t sbase = smem_u32(smem);

    const int tid  = threadIdx.x;
    const int lane = tid & 31;
    const int w    = tid >> 5;
    const int wm   = w & 3;          // 0..3  (M direction)
    const int wn   = w >> 2;         // 0..1  (N direction)

    const int bm = blockIdx.x & 63;  // 64 M-tiles
    const int bn = blockIdx.x >> 6;  // 32 N-tiles
    const int m0 = bm * BM;
    const int n0 = bn * BN;

    // ---- cp.async addressing (per thread: 8 x 16B chunks per stage) ----
    const int r0 = tid >> 3;         // 0..31 base row
    const int ch = tid & 7;          // chunk within 128B row
    const __nv_bfloat16* srcA = g_A + (size_t)(m0 + r0) * K_DIM + ch * 8;
    const __nv_bfloat16* srcW = g_W + (size_t)(n0 + r0) * K_DIM + ch * 8;
    const uint32_t dstA0 = sbase + r0 * ROW_BYTES + ch * 16;
    const uint32_t dstW0 = dstA0 + TILE_BYTES;

    #define LOAD_STAGE(s, ks) do {                                          \
        uint32_t _da = dstA0 + (s) * STAGE_BYTES;                           \
        uint32_t _dw = dstW0 + (s) * STAGE_BYTES;                           \
        const __nv_bfloat16* _sa = srcA + (ks) * BK;                        \
        const __nv_bfloat16* _sw = srcW + (ks) * BK;                        \
        _Pragma("unroll")                                                   \
        for (int _i = 0; _i < 4; ++_i)                                      \
            CP_ASYNC16(_da + _i * 32 * ROW_BYTES, _sa + (size_t)_i * 32 * K_DIM); \
        _Pragma("unroll")                                                   \
        for (int _i = 0; _i < 4; ++_i)                                      \
            CP_ASYNC16(_dw + _i * 32 * ROW_BYTES, _sw + (size_t)_i * 32 * K_DIM); \
    } while (0)

    // ---- ldmatrix addressing ----
    // A m16k16 frag: lanes 0-7 (m+l, k), 8-15 (m+8+l, k), 16-23 (m+l, k+8),
    //                24-31 (m+8+l, k+8)
    const uint32_t aAddr0 = sbase
        + (wm * 32 + (lane & 7) + ((lane >> 3) & 1) * 8) * ROW_BYTES
        + (lane >> 4) * 16;
    // B (n16k16 via x4): lanes 0-7 (n+l, k), 8-15 (n+l, k+8),
    //                    16-23 (n+8+l, k), 24-31 (n+8+l, k+8)
    const uint32_t bAddr0 = sbase + TILE_BYTES
        + (wn * 64 + (lane & 7) + ((lane >> 4) & 1) * 8) * ROW_BYTES
        + ((lane >> 3) & 1) * 16;

    float acc[2][8][4];
    #pragma unroll
    for (int i = 0; i < 2; ++i)
        #pragma unroll
        for (int j = 0; j < 8; ++j)
            #pragma unroll
            for (int q = 0; q < 4; ++q) acc[i][j][q] = 0.0f;

    // ---- prologue: fill ST-1 stages ----
    #pragma unroll
    for (int s = 0; s < ST - 1; ++s) {
        LOAD_STAGE(s, s);
        CP_COMMIT();
    }

    // ---- main loop ----
    for (int ks = 0; ks < KSTEPS; ++ks) {
        CP_WAIT2();
        __syncthreads();

        int nk = ks + ST - 1;
        if (nk < KSTEPS) LOAD_STAGE(nk & (ST - 1), nk);
        CP_COMMIT();

        const uint32_t aA = aAddr0 + (ks & (ST - 1)) * STAGE_BYTES;
        const uint32_t bA = bAddr0 + (ks & (ST - 1)) * STAGE_BYTES;

        #pragma unroll
        for (int kk = 0; kk < 4; ++kk) {            // 4 x k16 per stage
            uint32_t aF[2][4];
            #pragma unroll
            for (int im = 0; im < 2; ++im)
                LDSM_X4(aF[im], aA + im * 16 * ROW_BYTES + kk * 32);
            uint32_t bF[4][4];                      // [j]: n-tiles 2j, 2j+1
            #pragma unroll
            for (int j = 0; j < 4; ++j)
                LDSM_X4(bF[j], bA + j * 16 * ROW_BYTES + kk * 32);
            #pragma unroll
            for (int im = 0; im < 2; ++im)
                #pragma unroll
                for (int in = 0; in < 8; ++in)
                    MMA_BF16(acc[im][in], aF[im],
                             bF[in >> 1][(in & 1) * 2],
                             bF[in >> 1][(in & 1) * 2 + 1]);
        }
    }

    // ---- epilogue: fp32 + bias, direct float2 stores ----
    const int rowb = m0 + wm * 32 + (lane >> 2);
    const int colb = n0 + wn * 64 + (lane & 3) * 2;
    #pragma unroll
    for (int in = 0; in < 8; ++in) {
        const int col = colb + in * 8;
        const float2 bv = *reinterpret_cast<const float2*>(g_bias + col);
        #pragma unroll
        for (int im = 0; im < 2; ++im) {
            const int r = rowb + im * 16;
            float2 v0 = make_float2(acc[im][in][0] + bv.x, acc[im][in][1] + bv.y);
            float2 v1 = make_float2(acc[im][in][2] + bv.x, acc[im][in][3] + bv.y);
            *reinterpret_cast<float2*>(out + (size_t)r * F_DIM + col) = v0;
            *reinterpret_cast<float2*>(out + (size_t)(r + 8) * F_DIM + col) = v1;
        }
    }
}

// ---------------------------------------------------------------------------
// kernel_launch
// ---------------------------------------------------------------------------
extern "C" void kernel_launch(void* const* d_in, const int* in_sizes, int n_in,
                              void* d_out, int out_size) {
    (void)in_sizes; (void)n_in; (void)out_size;
    const float* x  = (const float*)d_in[0];
    const float* mu = (const float*)d_in[1];
    const float* sd = (const float*)d_in[2];
    float* out = (float*)d_out;

    prep_a_kernel<<<B_DIM, 256>>>(x);
    prep_w_kernel<<<F_DIM, 256>>>(mu, sd);

    static bool attr_set = false;
    if (!attr_set) {
        cudaFuncSetAttribute(gemm_kernel,
                             cudaFuncAttributeMaxDynamicSharedMemorySize, SMEM_DYN);
        attr_set = true;
    }
    gemm_kernel<<<(B_DIM / BM) * (F_DIM / BN), 256, SMEM_DYN>>>(out);
}

// round 3
// speedup vs baseline: 1.2764x; 1.2764x over previous
#include <cuda_runtime.h>
#include <cuda_bf16.h>
#include <cstdint>

// ============================================================================
// out[b,f] = -0.5 * sum_d ((x[b,d]-mu[f,d])/scale[f,d])^2
// One GEMM + bias:  out = A @ W^T + bias
//   A[b,:] = [ bf16(x^2) | bf16(x) ]             (8192 x 2048) bf16
//   W[f,:] = [ bf16(-0.5*inv2) | bf16(mu*inv2) ] (4096 x 2048) bf16
//   bias[f] = -0.5 * sum_d mu^2*inv2  (fp32 exact)
// R3 change: 3-stage pipeline @ 110.6KB SMEM -> 2 CTAs/SM (was 1) so barrier
// and cp.async waits of one CTA hide behind the other CTA's HMMA stream.
// ============================================================================

#define B_DIM 8192
#define F_DIM 4096
#define K_DIM 2048

#define BM 128
#define BN 128
#define BK 64
#define ST 3
#define LDS_ROW 72                      // 64 bf16 + 8 pad
#define ROW_BYTES (LDS_ROW * 2)         // 144 B (16B-aligned, LDSM conflict-free)
#define TILE_BYTES (BM * ROW_BYTES)     // 18432
#define STAGE_BYTES (2 * TILE_BYTES)    // 36864
#define SMEM_DYN (ST * STAGE_BYTES)     // 110592 -> 2 CTAs per SM
#define KSTEPS (K_DIM / BK)             // 32

__device__ __align__(16) __nv_bfloat16 g_A[(size_t)B_DIM * K_DIM];  // 32 MB
__device__ __align__(16) __nv_bfloat16 g_W[(size_t)F_DIM * K_DIM];  // 16 MB
__device__ float g_bias[F_DIM];

// ---------------------------------------------------------------------------
__device__ __forceinline__ uint32_t smem_u32(const void* p) {
    uint32_t a;
    asm("{ .reg .u64 t; cvta.to.shared.u64 t, %1; cvt.u32.u64 %0, t; }"
        : "=r"(a) : "l"(p));
    return a;
}

__device__ __forceinline__ uint32_t pack_bf16(float a, float b) {
    uint32_t lo = (uint32_t)__bfloat16_as_ushort(__float2bfloat16(a));
    uint32_t hi = (uint32_t)__bfloat16_as_ushort(__float2bfloat16(b));
    return lo | (hi << 16);
}

#define CP_ASYNC16(dst, src) \
    asm volatile("cp.async.cg.shared.global [%0], [%1], 16;" \
                 :: "r"(dst), "l"(src) : "memory")
#define CP_COMMIT() asm volatile("cp.async.commit_group;" ::: "memory")
#define CP_WAIT1()  asm volatile("cp.async.wait_group 1;" ::: "memory")

#define LDSM_X4(r, addr) \
    asm volatile("ldmatrix.sync.aligned.m8n8.x4.shared.b16 {%0,%1,%2,%3}, [%4];" \
                 : "=r"((r)[0]), "=r"((r)[1]), "=r"((r)[2]), "=r"((r)[3]) \
                 : "r"(addr))

#define MMA_BF16(c, a, b0, b1) \
    asm volatile("mma.sync.aligned.m16n8k16.row.col.f32.bf16.bf16.f32 " \
                 "{%0,%1,%2,%3}, {%4,%5,%6,%7}, {%8,%9}, {%0,%1,%2,%3};" \
                 : "+f"((c)[0]), "+f"((c)[1]), "+f"((c)[2]), "+f"((c)[3]) \
                 : "r"((a)[0]), "r"((a)[1]), "r"((a)[2]), "r"((a)[3]), \
                   "r"(b0), "r"(b1))

// ---------------------------------------------------------------------------
// Prep 1: A = [ bf16(x^2) | bf16(x) ]
// ---------------------------------------------------------------------------
__global__ void prep_a_kernel(const float* __restrict__ x) {
    int b = blockIdx.x;
    int t = threadIdx.x;
    float4 v = reinterpret_cast<const float4*>(x)[b * 256 + t];
    uint2 sq = make_uint2(pack_bf16(v.x * v.x, v.y * v.y),
                          pack_bf16(v.z * v.z, v.w * v.w));
    uint2 vr = make_uint2(pack_bf16(v.x, v.y), pack_bf16(v.z, v.w));
    uint2* A2 = reinterpret_cast<uint2*>(g_A);
    A2[(size_t)b * 512 + t]       = sq;
    A2[(size_t)b * 512 + 256 + t] = vr;
}

// ---------------------------------------------------------------------------
// Prep 2: W = [ bf16(-0.5*inv2) | bf16(mu*inv2) ], bias
// ---------------------------------------------------------------------------
__global__ void prep_w_kernel(const float* __restrict__ mu,
                              const float* __restrict__ sd) {
    __shared__ float red[256];
    int f = blockIdx.x;
    int t = threadIdx.x;
    float4 m = reinterpret_cast<const float4*>(mu)[f * 256 + t];
    float4 s = reinterpret_cast<const float4*>(sd)[f * 256 + t];
    float4 i2 = make_float4(1.0f / (s.x * s.x), 1.0f / (s.y * s.y),
                            1.0f / (s.z * s.z), 1.0f / (s.w * s.w));
    uint2 w1 = make_uint2(pack_bf16(-0.5f * i2.x, -0.5f * i2.y),
                          pack_bf16(-0.5f * i2.z, -0.5f * i2.w));
    uint2 w2 = make_uint2(pack_bf16(m.x * i2.x, m.y * i2.y),
                          pack_bf16(m.z * i2.z, m.w * i2.w));
    uint2* W2 = reinterpret_cast<uint2*>(g_W);
    W2[(size_t)f * 512 + t]       = w1;
    W2[(size_t)f * 512 + 256 + t] = w2;
    red[t] = m.x * m.x * i2.x + m.y * m.y * i2.y +
             m.z * m.z * i2.z + m.w * m.w * i2.w;
    __syncthreads();
    #pragma unroll
    for (int o = 128; o > 0; o >>= 1) {
        if (t < o) red[t] += red[t + o];
        __syncthreads();
    }
    if (t == 0) g_bias[f] = -0.5f * red[0];
}

// ---------------------------------------------------------------------------
// GEMM: 128x128 tile, BK=64, 3-stage cp.async pipe, 2 CTAs/SM,
// 8 warps (4m x 2n), warp tile 32x64, mma.sync m16n8k16 bf16->fp32
// ---------------------------------------------------------------------------
__global__ void __launch_bounds__(256, 2)
gemm_kernel(float* __restrict__ out) {
    extern __shared__ char smem[];
    const uint32_t sbase = smem_u32(smem);

    const int tid  = threadIdx.x;
    const int lane = tid & 31;
    const int w    = tid >> 5;
    const int wm   = w & 3;
    const int wn   = w >> 2;

    const int bm = blockIdx.x & 63;
    const int bn = blockIdx.x >> 6;
    const int m0 = bm * BM;
    const int n0 = bn * BN;

    // cp.async addressing: 256 threads x 8 chunks(16B) = full 128x64 bf16 tile
    const int r0 = tid >> 3;
    const int ch = tid & 7;
    const __nv_bfloat16* srcA = g_A + (size_t)(m0 + r0) * K_DIM + ch * 8;
    const __nv_bfloat16* srcW = g_W + (size_t)(n0 + r0) * K_DIM + ch * 8;
    const uint32_t dstA0 = sbase + r0 * ROW_BYTES + ch * 16;
    const uint32_t dstW0 = dstA0 + TILE_BYTES;

    #define LOAD_STAGE(s, ks) do {                                          \
        uint32_t _da = dstA0 + (s) * STAGE_BYTES;                           \
        uint32_t _dw = dstW0 + (s) * STAGE_BYTES;                           \
        const __nv_bfloat16* _sa = srcA + (ks) * BK;                        \
        const __nv_bfloat16* _sw = srcW + (ks) * BK;                        \
        _Pragma("unroll")                                                   \
        for (int _i = 0; _i < 4; ++_i)                                      \
            CP_ASYNC16(_da + _i * 32 * ROW_BYTES, _sa + (size_t)_i * 32 * K_DIM); \
        _Pragma("unroll")                                                   \
        for (int _i = 0; _i < 4; ++_i)                                      \
            CP_ASYNC16(_dw + _i * 32 * ROW_BYTES, _sw + (size_t)_i * 32 * K_DIM); \
    } while (0)

    // ldmatrix addressing
    const uint32_t aAddr0 = sbase
        + (wm * 32 + (lane & 7) + ((lane >> 3) & 1) * 8) * ROW_BYTES
        + (lane >> 4) * 16;
    const uint32_t bAddr0 = sbase + TILE_BYTES
        + (wn * 64 + (lane & 7) + ((lane >> 4) & 1) * 8) * ROW_BYTES
        + ((lane >> 3) & 1) * 16;

    float acc[2][8][4];
    #pragma unroll
    for (int i = 0; i < 2; ++i)
        #pragma unroll
        for (int j = 0; j < 8; ++j)
            #pragma unroll
            for (int q = 0; q < 4; ++q) acc[i][j][q] = 0.0f;

    // prologue: fill 2 stages
    LOAD_STAGE(0, 0);
    CP_COMMIT();
    LOAD_STAGE(1, 1);
    CP_COMMIT();

    int sc = 0;           // compute stage
    int sn = 2;           // next load stage
    for (int ks = 0; ks < KSTEPS; ++ks) {
        CP_WAIT1();
        __syncthreads();

        int nk = ks + 2;
        if (nk < KSTEPS) LOAD_STAGE(sn, nk);
        CP_COMMIT();
        sn = (sn == ST - 1) ? 0 : sn + 1;

        const uint32_t aA = aAddr0 + sc * STAGE_BYTES;
        const uint32_t bA = bAddr0 + sc * STAGE_BYTES;
        sc = (sc == ST - 1) ? 0 : sc + 1;

        #pragma unroll
        for (int kk = 0; kk < 4; ++kk) {
            uint32_t aF[2][4];
            #pragma unroll
            for (int im = 0; im < 2; ++im)
                LDSM_X4(aF[im], aA + im * 16 * ROW_BYTES + kk * 32);
            uint32_t bF[4][4];
            #pragma unroll
            for (int j = 0; j < 4; ++j)
                LDSM_X4(bF[j], bA + j * 16 * ROW_BYTES + kk * 32);
            #pragma unroll
            for (int im = 0; im < 2; ++im)
                #pragma unroll
                for (int in = 0; in < 8; ++in)
                    MMA_BF16(acc[im][in], aF[im],
                             bF[in >> 1][(in & 1) * 2],
                             bF[in >> 1][(in & 1) * 2 + 1]);
        }
    }

    // epilogue: fp32 + bias, float2 stores
    const int rowb = m0 + wm * 32 + (lane >> 2);
    const int colb = n0 + wn * 64 + (lane & 3) * 2;
    #pragma unroll
    for (int in = 0; in < 8; ++in) {
        const int col = colb + in * 8;
        const float2 bv = *reinterpret_cast<const float2*>(g_bias + col);
        #pragma unroll
        for (int im = 0; im < 2; ++im) {
            const int r = rowb + im * 16;
            float2 v0 = make_float2(acc[im][in][0] + bv.x, acc[im][in][1] + bv.y);
            float2 v1 = make_float2(acc[im][in][2] + bv.x, acc[im][in][3] + bv.y);
            *reinterpret_cast<float2*>(out + (size_t)r * F_DIM + col) = v0;
            *reinterpret_cast<float2*>(out + (size_t)(r + 8) * F_DIM + col) = v1;
        }
    }
}

// ---------------------------------------------------------------------------
extern "C" void kernel_launch(void* const* d_in, const int* in_sizes, int n_in,
                              void* d_out, int out_size) {
    (void)in_sizes; (void)n_in; (void)out_size;
    const float* x  = (const float*)d_in[0];
    const float* mu = (const float*)d_in[1];
    const float* sd = (const float*)d_in[2];
    float* out = (float*)d_out;

    prep_a_kernel<<<B_DIM, 256>>>(x);
    prep_w_kernel<<<F_DIM, 256>>>(mu, sd);

    static bool attr_set = false;
    if (!attr_set) {
        cudaFuncSetAttribute(gemm_kernel,
                             cudaFuncAttributeMaxDynamicSharedMemorySize, SMEM_DYN);
        attr_set = true;
    }
    gemm_kernel<<<(B_DIM / BM) * (F_DIM / BN), 256, SMEM_DYN>>>(out);
}